// round 15
// baseline (speedup 1.0000x reference)
#include <cuda_runtime.h>
#include <cuda_fp16.h>
#include <math.h>
#include <stdint.h>

#define BB    64
#define TT    256
#define IDIM  512
#define HDIM  1024
#define G4    4096        // 4*HDIM
#define GRID  64          // persistent blocks (1/SM, all resident)
#define HROW  72          // padded sub-buffer row stride in halfs (64 data + 8 pad)
#define SUBSZ (64 * HROW) // halfs per 64x64 sub-buffer
#define CKB   256         // staging chunk width in halfs (4 sub-buffers)

#define APAD  40          // gemm As row stride in halfs
#define BPAD  136         // gemm Bs row stride in halfs

#define NGRP  8           // barrier groups (8 blocks each)

// ---- device scratch ----
__device__ float    g_gates[(size_t)TT * BB * G4];  // [T][B][4H], bi+bh folded in
__device__ __half   g_h[2][BB * HDIM];              // double-buffered hidden state
__device__ unsigned g_cnt[NGRP * 32];               // barrier counters, 128B apart

// ---------------------------------------------------------------------------
// helpers
// ---------------------------------------------------------------------------
__device__ __forceinline__ void mma_f16(float d[4],
    uint32_t a0, uint32_t a1, uint32_t a2, uint32_t a3,
    uint32_t b0, uint32_t b1)
{
    asm volatile(
        "mma.sync.aligned.m16n8k16.row.col.f32.f16.f16.f32 "
        "{%0,%1,%2,%3},{%4,%5,%6,%7},{%8,%9},{%0,%1,%2,%3};\n"
        : "+f"(d[0]), "+f"(d[1]), "+f"(d[2]), "+f"(d[3])
        : "r"(a0), "r"(a1), "r"(a2), "r"(a3), "r"(b0), "r"(b1));
}

__device__ __forceinline__ void ldsm_x4(uint32_t& r0, uint32_t& r1,
                                        uint32_t& r2, uint32_t& r3,
                                        uint32_t smem_addr)
{
    asm volatile(
        "ldmatrix.sync.aligned.m8n8.x4.shared.b16 {%0,%1,%2,%3}, [%4];"
        : "=r"(r0), "=r"(r1), "=r"(r2), "=r"(r3)
        : "r"(smem_addr));
}

__device__ __forceinline__ void ldsm_x2_trans(uint32_t& r0, uint32_t& r1,
                                              uint32_t smem_addr)
{
    asm volatile(
        "ldmatrix.sync.aligned.m8n8.x2.trans.shared.b16 {%0,%1}, [%2];"
        : "=r"(r0), "=r"(r1)
        : "r"(smem_addr));
}

__device__ __forceinline__ float sigf(float x) {
    return 1.f / (1.f + __expf(-x));
}

// ---------------------------------------------------------------------------
// Phase 1: gates = x @ Wi + bi + bh   (fp16 MMA, unchanged from R13/R14)
// Block (0,0) zeroes the barrier counters.
// ---------------------------------------------------------------------------
__global__ void __launch_bounds__(256, 2) gemm_f16_kernel(
    const float* __restrict__ X,   // [16384, 512]
    const float* __restrict__ Wi,  // [512, 4096]
    const float* __restrict__ bi,  // [4096]
    const float* __restrict__ bh)  // [4096]
{
    if (blockIdx.x == 0 && blockIdx.y == 0 && threadIdx.x < NGRP)
        g_cnt[threadIdx.x * 32] = 0u;

    __shared__ __half As[128][APAD];
    __shared__ __half Bs[32][BPAD];

    const int tid  = threadIdx.x;
    const int lane = tid & 31;
    const int w    = tid >> 5;
    const int wm   = w & 1;
    const int wn   = w >> 1;
    const int m0   = blockIdx.y * 128;
    const int n0   = blockIdx.x * 128;

    const int rowg = lane >> 2;
    const int kq   = lane & 3;

    const int aRow = tid >> 1;
    const int aKh  = (tid & 1) * 16;
    const int bK   = tid >> 5;
    const int bN   = (tid & 31) * 4;

    float acc[4][4][4];
#pragma unroll
    for (int mi = 0; mi < 4; mi++)
#pragma unroll
        for (int ni = 0; ni < 4; ni++)
#pragma unroll
            for (int q = 0; q < 4; q++) acc[mi][ni][q] = 0.f;

    const uint32_t asB = (uint32_t)__cvta_generic_to_shared(&As[0][0]);
    const uint32_t bsB = (uint32_t)__cvta_generic_to_shared(&Bs[0][0]);

    float4 pa[4], pb[4];
#pragma unroll
    for (int i = 0; i < 4; i++)
        pa[i] = *(const float4*)(X + (size_t)(m0 + aRow) * IDIM + aKh + i * 4);
#pragma unroll
    for (int h = 0; h < 4; h++)
        pb[h] = *(const float4*)(Wi + (size_t)(bK + h * 8) * G4 + n0 + bN);

    for (int k0 = 0; k0 < IDIM; k0 += 32) {
        {
            __half2 q0 = __floats2half2_rn(pa[0].x, pa[0].y);
            __half2 q1 = __floats2half2_rn(pa[0].z, pa[0].w);
            __half2 q2 = __floats2half2_rn(pa[1].x, pa[1].y);
            __half2 q3 = __floats2half2_rn(pa[1].z, pa[1].w);
            uint4 v0;
            v0.x = *(uint32_t*)&q0; v0.y = *(uint32_t*)&q1;
            v0.z = *(uint32_t*)&q2; v0.w = *(uint32_t*)&q3;
            *(uint4*)(&As[aRow][aKh]) = v0;
            q0 = __floats2half2_rn(pa[2].x, pa[2].y);
            q1 = __floats2half2_rn(pa[2].z, pa[2].w);
            q2 = __floats2half2_rn(pa[3].x, pa[3].y);
            q3 = __floats2half2_rn(pa[3].z, pa[3].w);
            uint4 v1;
            v1.x = *(uint32_t*)&q0; v1.y = *(uint32_t*)&q1;
            v1.z = *(uint32_t*)&q2; v1.w = *(uint32_t*)&q3;
            *(uint4*)(&As[aRow][aKh + 8]) = v1;
        }
#pragma unroll
        for (int h = 0; h < 4; h++) {
            __half2 q0 = __floats2half2_rn(pb[h].x, pb[h].y);
            __half2 q1 = __floats2half2_rn(pb[h].z, pb[h].w);
            uint2 v;
            v.x = *(uint32_t*)&q0; v.y = *(uint32_t*)&q1;
            *(uint2*)(&Bs[bK + h * 8][bN]) = v;
        }
        __syncthreads();

        if (k0 + 32 < IDIM) {
            int kn = k0 + 32;
#pragma unroll
            for (int i = 0; i < 4; i++)
                pa[i] = *(const float4*)(X + (size_t)(m0 + aRow) * IDIM + kn + aKh + i * 4);
#pragma unroll
            for (int h = 0; h < 4; h++)
                pb[h] = *(const float4*)(Wi + (size_t)(kn + bK + h * 8) * G4 + n0 + bN);
        }

#pragma unroll
        for (int ks = 0; ks < 2; ks++) {
            uint32_t af[4][4], bf[4][2];
#pragma unroll
            for (int mi = 0; mi < 4; mi++) {
                uint32_t addr = asB
                    + (uint32_t)((wm * 64 + mi * 16 + (lane & 15)) * APAD * 2)
                    + (uint32_t)(ks * 32) + ((lane & 16) ? 16u : 0u);
                ldsm_x4(af[mi][0], af[mi][1], af[mi][2], af[mi][3], addr);
            }
#pragma unroll
            for (int ni = 0; ni < 4; ni++) {
                uint32_t addr = bsB
                    + (uint32_t)((ks * 16 + (lane & 15)) * BPAD * 2)
                    + (uint32_t)((wn * 32 + ni * 8) * 2);
                ldsm_x2_trans(bf[ni][0], bf[ni][1], addr);
            }
#pragma unroll
            for (int mi = 0; mi < 4; mi++)
#pragma unroll
                for (int ni = 0; ni < 4; ni++)
                    mma_f16(acc[mi][ni], af[mi][0], af[mi][1], af[mi][2], af[mi][3],
                            bf[ni][0], bf[ni][1]);
        }
        __syncthreads();
    }

#pragma unroll
    for (int ni = 0; ni < 4; ni++) {
        int n = n0 + wn * 32 + ni * 8 + 2 * kq;
        float bias0 = bi[n] + bh[n];
        float bias1 = bi[n + 1] + bh[n + 1];
#pragma unroll
        for (int mi = 0; mi < 4; mi++) {
            int m  = m0 + wm * 64 + mi * 16 + rowg;
            {
                int b = m >> 8, t = m & 255;
                float2 v = make_float2(acc[mi][ni][0] + bias0, acc[mi][ni][1] + bias1);
                *(float2*)(g_gates + (size_t)(t * BB + b) * G4 + n) = v;
            }
            {
                int m2 = m + 8;
                int b = m2 >> 8, t = m2 & 255;
                float2 v = make_float2(acc[mi][ni][2] + bias0, acc[mi][ni][3] + bias1);
                *(float2*)(g_gates + (size_t)(t * BB + b) * G4 + n) = v;
            }
        }
    }
}

// ---------------------------------------------------------------------------
// Phase 2: persistent LSTM recurrence.
// Change vs R14: GRID 128 -> 64; each block owns 16 hidden units (64 gate
// cols). Wfq doubled to [64 s][4 idx][32 lanes] (128 KB); acc/creg/gates/
// epilogue scaled x2. Staging, LDSM addressing, barrier form unchanged.
// ---------------------------------------------------------------------------
__global__ void __launch_bounds__(256, 1) lstm_persist_kernel(
    const float* __restrict__ Wh,   // [1024, 4096]
    float* __restrict__ out)        // Q_all | hT | cT
{
    extern __shared__ char smem[];
    uint4*  Wfq = (uint4*)smem;                      // [64 s][4 idx][32 lanes] = 128 KB
    __half* Hs  = (__half*)(smem + 131072);          // 2 * 4 * SUBSZ halfs

    const int tid  = threadIdx.x;
    const int lane = tid & 31;
    const int wid  = tid >> 5;
    const int wm   = wid & 3;
    const int wn   = wid >> 2;
    const int bx   = blockIdx.x;

    // build Wfq: idx = wn*2 + nt2 packs gate-col n8-tiles {2*idx, 2*idx+1}
    // n in [0,64): j = bx*16 + (n>>2), g = n&3
    for (int e = tid; e < 64 * 4 * 32; e += 256) {
        int l   = e & 31;
        int idx = (e >> 5) & 3;
        int s   = e >> 7;
        int k   = s * 16 + (l & 3) * 2;
        uint32_t vals[4];
#pragma unroll
        for (int half = 0; half < 2; half++) {
            int ct = idx * 2 + half;
            int n  = ct * 8 + (l >> 2);
            int j  = bx * 16 + (n >> 2);
            int g  = n & 3;
            const float* Wcol = Wh + (size_t)g * 1024 + j;
            __half2 h0 = __floats2half2_rn(Wcol[(size_t)k * G4],
                                           Wcol[(size_t)(k + 1) * G4]);
            __half2 h1 = __floats2half2_rn(Wcol[(size_t)(k + 8) * G4],
                                           Wcol[(size_t)(k + 9) * G4]);
            vals[half * 2]     = *(uint32_t*)&h0;
            vals[half * 2 + 1] = *(uint32_t*)&h1;
        }
        Wfq[e] = make_uint4(vals[0], vals[1], vals[2], vals[3]);
    }
    __syncthreads();

    const int kq   = lane & 3;
    const int rowg = lane >> 2;
    const int odd  = lane & 1;
    const int bmy  = wm * 16 + rowg + (odd ? 8 : 0);
    const int jbase = bx * 16 + wn * 8 + (kq >> 1);   // + nt*2, nt in 0..3

    float creg[4] = {0.f, 0.f, 0.f, 0.f};

    const uint32_t hsB = (uint32_t)__cvta_generic_to_shared(Hs);
    const uint32_t laneA = hsB
        + (uint32_t)((wm * 16 + (lane & 15)) * HROW) * 2
        + ((lane & 16) ? 16u : 0u);

    const int sb = tid >> 3;
    const int sg = tid & 7;

    unsigned* const my_cnt = &g_cnt[(bx >> 3) * 32];

    for (int t = 0; t < TT; t++) {
        float acc[4][4];
#pragma unroll
        for (int nt = 0; nt < 4; nt++)
#pragma unroll
            for (int q = 0; q < 4; q++) acc[nt][q] = 0.f;

        const float* __restrict__ gt = g_gates + (size_t)t * BB * G4;
        float gF[4], gI[4], gA[4], gO[4];
#pragma unroll
        for (int nt = 0; nt < 4; nt++) {
            int j = jbase + nt * 2;
            gF[nt] = __ldcg(gt + (size_t)bmy * G4 + j);
            gI[nt] = __ldcg(gt + (size_t)bmy * G4 + 1024 + j);
            gA[nt] = __ldcg(gt + (size_t)bmy * G4 + 2048 + j);
            gO[nt] = __ldcg(gt + (size_t)bmy * G4 + 3072 + j);
        }

        if (t > 0) {
            // ---- grid barrier: distributed arrive + direct poll (R14 form) ----
            __threadfence();
            __syncthreads();
            if (wid == 0) {
                if (lane == 0)
                    asm volatile("red.release.gpu.global.add.u32 [%0], %1;"
                                 :: "l"(my_cnt), "r"(1u) : "memory");
                if (lane < NGRP) {
                    const unsigned* p = &g_cnt[lane * 32];
                    const unsigned target = (unsigned)t * (GRID / NGRP);
                    unsigned v;
                    for (;;) {
                        asm volatile("ld.global.acquire.gpu.u32 %0, [%1];"
                                     : "=r"(v) : "l"(p) : "memory");
                        if (v >= target) break;
                        __nanosleep(64);
                    }
                }
            }
            __syncthreads();

            const __half* __restrict__ hin = g_h[t & 1];

            uint4 pf[2][4];
#pragma unroll
            for (int i = 0; i < 2; i++) {
                int b = sb + i * 32;
#pragma unroll
                for (int q = 0; q < 4; q++)
                    pf[i][q] = __ldcg((const uint4*)(hin + (size_t)b * HDIM
                                                     + q * 64 + sg * 8));
            }

            int buf = 0;
            for (int ch = 0; ch < 4; ch++) {
                {
                    __half* H = Hs + buf * (4 * SUBSZ);
#pragma unroll
                    for (int i = 0; i < 2; i++) {
                        int b = sb + i * 32;
#pragma unroll
                        for (int q = 0; q < 4; q++)
                            *(uint4*)(H + q * SUBSZ + b * HROW + sg * 8) = pf[i][q];
                    }
                }
                __syncthreads();

                if (ch < 3) {
                    int k0 = (ch + 1) * CKB;
#pragma unroll
                    for (int i = 0; i < 2; i++) {
                        int b = sb + i * 32;
#pragma unroll
                        for (int q = 0; q < 4; q++)
                            pf[i][q] = __ldcg((const uint4*)(hin + (size_t)b * HDIM
                                                             + k0 + q * 64 + sg * 8));
                    }
                }

                const uint32_t chunkA = laneA + (uint32_t)(buf * (4 * SUBSZ * 2));
#pragma unroll
                for (int ks = 0; ks < 16; ks++) {
                    int q   = ks >> 2;
                    int kss = ks & 3;
                    uint32_t a0, a1, a2, a3;
                    ldsm_x4(a0, a1, a2, a3,
                            chunkA + (uint32_t)(q * (SUBSZ * 2) + kss * 32));
                    int s = ch * 16 + ks;
#pragma unroll
                    for (int nt2 = 0; nt2 < 2; nt2++) {
                        uint4 bv = Wfq[(s * 4 + wn * 2 + nt2) * 32 + lane];
                        mma_f16(acc[nt2 * 2],     a0, a1, a2, a3, bv.x, bv.y);
                        mma_f16(acc[nt2 * 2 + 1], a0, a1, a2, a3, bv.z, bv.w);
                    }
                }
                buf ^= 1;
            }
            __syncthreads();
        }

        // ---- epilogue (x2 scaled) ----
        __half* __restrict__ hout = g_h[(t + 1) & 1];
#pragma unroll
        for (int nt = 0; nt < 4; nt++) {
            float x0 = __shfl_xor_sync(0xffffffffu, acc[nt][0], 1);
            float x1 = __shfl_xor_sync(0xffffffffu, acc[nt][1], 1);
            float x2 = __shfl_xor_sync(0xffffffffu, acc[nt][2], 1);
            float x3 = __shfl_xor_sync(0xffffffffu, acc[nt][3], 1);

            float F, I, A, O;
            if (!odd) { F = acc[nt][0]; I = acc[nt][1]; A = x0; O = x1; }
            else      { F = x2;         I = x3;         A = acc[nt][2]; O = acc[nt][3]; }

            F += gF[nt]; I += gI[nt]; A += gA[nt]; O += gO[nt];

            float f = sigf(F);
            float i = sigf(I);
            float a = tanhf(A);
            float o = sigf(O);

            float c = f * creg[nt] + i * a;
            creg[nt] = c;
            float h = o * tanhf(c);

            int j = jbase + nt * 2;
            hout[(size_t)bmy * HDIM + j] = __float2half(h);
            out[((size_t)bmy * TT + t) * HDIM + j] = h;
            if (t == TT - 1) {
                size_t qsz = (size_t)BB * TT * HDIM;
                out[qsz + (size_t)bmy * HDIM + j]             = h;
                out[qsz + BB * HDIM + (size_t)bmy * HDIM + j] = c;
            }
        }
    }
}

// ---------------------------------------------------------------------------
extern "C" void kernel_launch(void* const* d_in, const int* in_sizes, int n_in,
                              void* d_out, int out_size) {
    const float* x  = (const float*)d_in[0];
    const float* Wi = (const float*)d_in[1];
    const float* bi = (const float*)d_in[2];
    const float* Wh = (const float*)d_in[3];
    const float* bh = (const float*)d_in[4];
    float* out = (float*)d_out;

    const int smem_bytes = 131072 + 2 * 4 * SUBSZ * 2;   // 204,800 B
    cudaFuncSetAttribute(lstm_persist_kernel,
                         cudaFuncAttributeMaxDynamicSharedMemorySize, smem_bytes);

    gemm_f16_kernel<<<dim3(G4 / 128, (BB * TT) / 128), 256>>>(x, Wi, bi, bh);
    lstm_persist_kernel<<<GRID, 256, smem_bytes>>>(Wh, out);
}

// round 16
// speedup vs baseline: 1.1658x; 1.1658x over previous
#include <cuda_runtime.h>
#include <cuda_fp16.h>
#include <math.h>
#include <stdint.h>

#define BB    64
#define TT    256
#define IDIM  512
#define HDIM  1024
#define G4    4096        // 4*HDIM
#define GRID  128         // persistent blocks (<=148, all resident)
#define HROW  72          // padded sub-buffer row stride in halfs (64 data + 8 pad)
#define SUBSZ (64 * HROW) // halfs per 64x64 sub-buffer
#define CKB   256         // staging chunk width in halfs (4 sub-buffers)

#define APAD  40          // gemm As row stride in halfs
#define BPAD  136         // gemm Bs row stride in halfs

#define NQ    4           // quarter-barrier counters (32 producer blocks each)

// ---- device scratch ----
__device__ float    g_gates[(size_t)TT * BB * G4];  // [T][B][4H], bi+bh folded in
__device__ __half   g_h[2][BB * HDIM];              // double-buffered hidden state
__device__ unsigned g_cnt[NQ * 32];                 // quarter counters, 128B apart

// ---------------------------------------------------------------------------
// helpers
// ---------------------------------------------------------------------------
__device__ __forceinline__ void mma_f16(float d[4],
    uint32_t a0, uint32_t a1, uint32_t a2, uint32_t a3,
    uint32_t b0, uint32_t b1)
{
    asm volatile(
        "mma.sync.aligned.m16n8k16.row.col.f32.f16.f16.f32 "
        "{%0,%1,%2,%3},{%4,%5,%6,%7},{%8,%9},{%0,%1,%2,%3};\n"
        : "+f"(d[0]), "+f"(d[1]), "+f"(d[2]), "+f"(d[3])
        : "r"(a0), "r"(a1), "r"(a2), "r"(a3), "r"(b0), "r"(b1));
}

__device__ __forceinline__ void ldsm_x4(uint32_t& r0, uint32_t& r1,
                                        uint32_t& r2, uint32_t& r3,
                                        uint32_t smem_addr)
{
    asm volatile(
        "ldmatrix.sync.aligned.m8n8.x4.shared.b16 {%0,%1,%2,%3}, [%4];"
        : "=r"(r0), "=r"(r1), "=r"(r2), "=r"(r3)
        : "r"(smem_addr));
}

__device__ __forceinline__ void ldsm_x2_trans(uint32_t& r0, uint32_t& r1,
                                              uint32_t smem_addr)
{
    asm volatile(
        "ldmatrix.sync.aligned.m8n8.x2.trans.shared.b16 {%0,%1}, [%2];"
        : "=r"(r0), "=r"(r1)
        : "r"(smem_addr));
}

__device__ __forceinline__ float sigf(float x) {
    return 1.f / (1.f + __expf(-x));
}

// acquire-poll a quarter counter until it reaches target (per-thread scalar spin)
__device__ __forceinline__ void wait_quarter(const unsigned* p, unsigned target) {
    unsigned v;
    for (;;) {
        asm volatile("ld.global.acquire.gpu.u32 %0, [%1];"
                     : "=r"(v) : "l"(p) : "memory");
        if (v >= target) break;
        __nanosleep(32);
    }
}

// ---------------------------------------------------------------------------
// Phase 1: gates = x @ Wi + bi + bh   (fp16 MMA, unchanged from R13/R14)
// Block (0,0) zeroes the quarter counters.
// ---------------------------------------------------------------------------
__global__ void __launch_bounds__(256, 2) gemm_f16_kernel(
    const float* __restrict__ X,   // [16384, 512]
    const float* __restrict__ Wi,  // [512, 4096]
    const float* __restrict__ bi,  // [4096]
    const float* __restrict__ bh)  // [4096]
{
    if (blockIdx.x == 0 && blockIdx.y == 0 && threadIdx.x < NQ)
        g_cnt[threadIdx.x * 32] = 0u;

    __shared__ __half As[128][APAD];
    __shared__ __half Bs[32][BPAD];

    const int tid  = threadIdx.x;
    const int lane = tid & 31;
    const int w    = tid >> 5;
    const int wm   = w & 1;
    const int wn   = w >> 1;
    const int m0   = blockIdx.y * 128;
    const int n0   = blockIdx.x * 128;

    const int rowg = lane >> 2;
    const int kq   = lane & 3;

    const int aRow = tid >> 1;
    const int aKh  = (tid & 1) * 16;
    const int bK   = tid >> 5;
    const int bN   = (tid & 31) * 4;

    float acc[4][4][4];
#pragma unroll
    for (int mi = 0; mi < 4; mi++)
#pragma unroll
        for (int ni = 0; ni < 4; ni++)
#pragma unroll
            for (int q = 0; q < 4; q++) acc[mi][ni][q] = 0.f;

    const uint32_t asB = (uint32_t)__cvta_generic_to_shared(&As[0][0]);
    const uint32_t bsB = (uint32_t)__cvta_generic_to_shared(&Bs[0][0]);

    float4 pa[4], pb[4];
#pragma unroll
    for (int i = 0; i < 4; i++)
        pa[i] = *(const float4*)(X + (size_t)(m0 + aRow) * IDIM + aKh + i * 4);
#pragma unroll
    for (int h = 0; h < 4; h++)
        pb[h] = *(const float4*)(Wi + (size_t)(bK + h * 8) * G4 + n0 + bN);

    for (int k0 = 0; k0 < IDIM; k0 += 32) {
        {
            __half2 q0 = __floats2half2_rn(pa[0].x, pa[0].y);
            __half2 q1 = __floats2half2_rn(pa[0].z, pa[0].w);
            __half2 q2 = __floats2half2_rn(pa[1].x, pa[1].y);
            __half2 q3 = __floats2half2_rn(pa[1].z, pa[1].w);
            uint4 v0;
            v0.x = *(uint32_t*)&q0; v0.y = *(uint32_t*)&q1;
            v0.z = *(uint32_t*)&q2; v0.w = *(uint32_t*)&q3;
            *(uint4*)(&As[aRow][aKh]) = v0;
            q0 = __floats2half2_rn(pa[2].x, pa[2].y);
            q1 = __floats2half2_rn(pa[2].z, pa[2].w);
            q2 = __floats2half2_rn(pa[3].x, pa[3].y);
            q3 = __floats2half2_rn(pa[3].z, pa[3].w);
            uint4 v1;
            v1.x = *(uint32_t*)&q0; v1.y = *(uint32_t*)&q1;
            v1.z = *(uint32_t*)&q2; v1.w = *(uint32_t*)&q3;
            *(uint4*)(&As[aRow][aKh + 8]) = v1;
        }
#pragma unroll
        for (int h = 0; h < 4; h++) {
            __half2 q0 = __floats2half2_rn(pb[h].x, pb[h].y);
            __half2 q1 = __floats2half2_rn(pb[h].z, pb[h].w);
            uint2 v;
            v.x = *(uint32_t*)&q0; v.y = *(uint32_t*)&q1;
            *(uint2*)(&Bs[bK + h * 8][bN]) = v;
        }
        __syncthreads();

        if (k0 + 32 < IDIM) {
            int kn = k0 + 32;
#pragma unroll
            for (int i = 0; i < 4; i++)
                pa[i] = *(const float4*)(X + (size_t)(m0 + aRow) * IDIM + kn + aKh + i * 4);
#pragma unroll
            for (int h = 0; h < 4; h++)
                pb[h] = *(const float4*)(Wi + (size_t)(kn + bK + h * 8) * G4 + n0 + bN);
        }

#pragma unroll
        for (int ks = 0; ks < 2; ks++) {
            uint32_t af[4][4], bf[4][2];
#pragma unroll
            for (int mi = 0; mi < 4; mi++) {
                uint32_t addr = asB
                    + (uint32_t)((wm * 64 + mi * 16 + (lane & 15)) * APAD * 2)
                    + (uint32_t)(ks * 32) + ((lane & 16) ? 16u : 0u);
                ldsm_x4(af[mi][0], af[mi][1], af[mi][2], af[mi][3], addr);
            }
#pragma unroll
            for (int ni = 0; ni < 4; ni++) {
                uint32_t addr = bsB
                    + (uint32_t)((ks * 16 + (lane & 15)) * BPAD * 2)
                    + (uint32_t)((wn * 32 + ni * 8) * 2);
                ldsm_x2_trans(bf[ni][0], bf[ni][1], addr);
            }
#pragma unroll
            for (int mi = 0; mi < 4; mi++)
#pragma unroll
                for (int ni = 0; ni < 4; ni++)
                    mma_f16(acc[mi][ni], af[mi][0], af[mi][1], af[mi][2], af[mi][3],
                            bf[ni][0], bf[ni][1]);
        }
        __syncthreads();
    }

#pragma unroll
    for (int ni = 0; ni < 4; ni++) {
        int n = n0 + wn * 32 + ni * 8 + 2 * kq;
        float bias0 = bi[n] + bh[n];
        float bias1 = bi[n + 1] + bh[n + 1];
#pragma unroll
        for (int mi = 0; mi < 4; mi++) {
            int m  = m0 + wm * 64 + mi * 16 + rowg;
            {
                int b = m >> 8, t = m & 255;
                float2 v = make_float2(acc[mi][ni][0] + bias0, acc[mi][ni][1] + bias1);
                *(float2*)(g_gates + (size_t)(t * BB + b) * G4 + n) = v;
            }
            {
                int m2 = m + 8;
                int b = m2 >> 8, t = m2 & 255;
                float2 v = make_float2(acc[mi][ni][2] + bias0, acc[mi][ni][3] + bias1);
                *(float2*)(g_gates + (size_t)(t * BB + b) * G4 + n) = v;
            }
        }
    }
}

// ---------------------------------------------------------------------------
// Phase 2: persistent LSTM recurrence (R14 skeleton: 128 blocks, 8 j-units,
// 4 double-buffered 256-col chunks).
// ONLY change: monolithic grid barrier -> 4 pipelined quarter-barriers.
//   Chunk q of h (cols [256q,256q+256)) is produced by blocks [32q,32q+32).
//   arrive: red.release.add to counter[bx>>5] after fencing h stores.
//   wait:   all threads acquire-poll counter[q] >= 32*t just before
//           prefetching chunk q -> chunk 0 starts at 1/4 arrival, and the
//           wait for quarter q overlaps with mma of chunk q-1.
// ---------------------------------------------------------------------------
__global__ void __launch_bounds__(256, 1) lstm_persist_kernel(
    const float* __restrict__ Wh,   // [1024, 4096]
    float* __restrict__ out)        // Q_all | hT | cT
{
    extern __shared__ char smem[];
    uint4*  Wfq = (uint4*)smem;                      // [64 s][2 wn][32 lanes] = 64 KB
    __half* Hs  = (__half*)(smem + 65536);           // 2 * 4 * SUBSZ halfs

    const int tid  = threadIdx.x;
    const int lane = tid & 31;
    const int wid  = tid >> 5;
    const int wm   = wid & 3;
    const int wn   = wid >> 2;
    const int bx   = blockIdx.x;

    for (int e = tid; e < 64 * 2 * 32; e += 256) {
        int l  = e & 31;
        int w2 = (e >> 5) & 1;
        int s  = e >> 6;
        int k  = s * 16 + (l & 3) * 2;
        uint32_t vals[4];
#pragma unroll
        for (int nt = 0; nt < 2; nt++) {
            int ct = w2 * 2 + nt;
            int n  = ct * 8 + (l >> 2);
            int j  = bx * 8 + (n >> 2);
            int g  = n & 3;
            const float* Wcol = Wh + (size_t)g * 1024 + j;
            __half2 h0 = __floats2half2_rn(Wcol[(size_t)k * G4],
                                           Wcol[(size_t)(k + 1) * G4]);
            __half2 h1 = __floats2half2_rn(Wcol[(size_t)(k + 8) * G4],
                                           Wcol[(size_t)(k + 9) * G4]);
            vals[nt * 2]     = *(uint32_t*)&h0;
            vals[nt * 2 + 1] = *(uint32_t*)&h1;
        }
        Wfq[e] = make_uint4(vals[0], vals[1], vals[2], vals[3]);
    }
    __syncthreads();

    const int kq   = lane & 3;
    const int rowg = lane >> 2;
    const int odd  = lane & 1;
    const int bmy  = wm * 16 + rowg + (odd ? 8 : 0);
    const int jbase = bx * 8 + wn * 4 + (kq >> 1);

    float creg[2] = {0.f, 0.f};

    const uint32_t hsB = (uint32_t)__cvta_generic_to_shared(Hs);
    const uint32_t laneA = hsB
        + (uint32_t)((wm * 16 + (lane & 15)) * HROW) * 2
        + ((lane & 16) ? 16u : 0u);

    const int sb = tid >> 3;
    const int sg = tid & 7;

    unsigned* const my_cnt = &g_cnt[(bx >> 5) * 32];

    for (int t = 0; t < TT; t++) {
        float acc[2][4] = {{0.f,0.f,0.f,0.f},{0.f,0.f,0.f,0.f}};

        const float* __restrict__ gt = g_gates + (size_t)t * BB * G4;
        float gF[2], gI[2], gA[2], gO[2];
#pragma unroll
        for (int nt = 0; nt < 2; nt++) {
            int j = jbase + nt * 2;
            gF[nt] = __ldcg(gt + (size_t)bmy * G4 + j);
            gI[nt] = __ldcg(gt + (size_t)bmy * G4 + 1024 + j);
            gA[nt] = __ldcg(gt + (size_t)bmy * G4 + 2048 + j);
            gO[nt] = __ldcg(gt + (size_t)bmy * G4 + 3072 + j);
        }

        if (t > 0) {
            // ---- arrive: my h[t] slice (written end of step t-1) is ready ----
            __threadfence();
            __syncthreads();
            if (tid == 0)
                asm volatile("red.release.gpu.global.add.u32 [%0], %1;"
                             :: "l"(my_cnt), "r"(1u) : "memory");

            const __half* __restrict__ hin = g_h[t & 1];
            const unsigned qtarget = (unsigned)t * 32u;

            // ---- wait quarter 0, prefetch chunk 0 ----
            wait_quarter(&g_cnt[0], qtarget);
            uint4 pf[2][4];
#pragma unroll
            for (int i = 0; i < 2; i++) {
                int b = sb + i * 32;
#pragma unroll
                for (int q = 0; q < 4; q++)
                    pf[i][q] = __ldcg((const uint4*)(hin + (size_t)b * HDIM
                                                     + q * 64 + sg * 8));
            }

            int buf = 0;
            for (int ch = 0; ch < 4; ch++) {
                {
                    __half* H = Hs + buf * (4 * SUBSZ);
#pragma unroll
                    for (int i = 0; i < 2; i++) {
                        int b = sb + i * 32;
#pragma unroll
                        for (int q = 0; q < 4; q++)
                            *(uint4*)(H + q * SUBSZ + b * HROW + sg * 8) = pf[i][q];
                    }
                }
                __syncthreads();

                if (ch < 3) {
                    // ---- wait quarter ch+1, then prefetch its chunk ----
                    wait_quarter(&g_cnt[(ch + 1) * 32], qtarget);
                    int k0 = (ch + 1) * CKB;
#pragma unroll
                    for (int i = 0; i < 2; i++) {
                        int b = sb + i * 32;
#pragma unroll
                        for (int q = 0; q < 4; q++)
                            pf[i][q] = __ldcg((const uint4*)(hin + (size_t)b * HDIM
                                                             + k0 + q * 64 + sg * 8));
                    }
                }

                const uint32_t chunkA = laneA + (uint32_t)(buf * (4 * SUBSZ * 2));
#pragma unroll
                for (int ks = 0; ks < 16; ks++) {
                    int q   = ks >> 2;
                    int kss = ks & 3;
                    uint32_t a0, a1, a2, a3;
                    ldsm_x4(a0, a1, a2, a3,
                            chunkA + (uint32_t)(q * (SUBSZ * 2) + kss * 32));
                    int s = ch * 16 + ks;
                    uint4 bv = Wfq[(s * 2 + wn) * 32 + lane];
                    mma_f16(acc[0], a0, a1, a2, a3, bv.x, bv.y);
                    mma_f16(acc[1], a0, a1, a2, a3, bv.z, bv.w);
                }
                buf ^= 1;
            }
            __syncthreads();
        }

        // ---- epilogue (unchanged) ----
        __half* __restrict__ hout = g_h[(t + 1) & 1];
#pragma unroll
        for (int nt = 0; nt < 2; nt++) {
            float x0 = __shfl_xor_sync(0xffffffffu, acc[nt][0], 1);
            float x1 = __shfl_xor_sync(0xffffffffu, acc[nt][1], 1);
            float x2 = __shfl_xor_sync(0xffffffffu, acc[nt][2], 1);
            float x3 = __shfl_xor_sync(0xffffffffu, acc[nt][3], 1);

            float F, I, A, O;
            if (!odd) { F = acc[nt][0]; I = acc[nt][1]; A = x0; O = x1; }
            else      { F = x2;         I = x3;         A = acc[nt][2]; O = acc[nt][3]; }

            F += gF[nt]; I += gI[nt]; A += gA[nt]; O += gO[nt];

            float f = sigf(F);
            float i = sigf(I);
            float a = tanhf(A);
            float o = sigf(O);

            float c = f * creg[nt] + i * a;
            creg[nt] = c;
            float h = o * tanhf(c);

            int j = jbase + nt * 2;
            hout[(size_t)bmy * HDIM + j] = __float2half(h);
            out[((size_t)bmy * TT + t) * HDIM + j] = h;
            if (t == TT - 1) {
                size_t qsz = (size_t)BB * TT * HDIM;
                out[qsz + (size_t)bmy * HDIM + j]             = h;
                out[qsz + BB * HDIM + (size_t)bmy * HDIM + j] = c;
            }
        }
    }
}

// ---------------------------------------------------------------------------
extern "C" void kernel_launch(void* const* d_in, const int* in_sizes, int n_in,
                              void* d_out, int out_size) {
    const float* x  = (const float*)d_in[0];
    const float* Wi = (const float*)d_in[1];
    const float* bi = (const float*)d_in[2];
    const float* Wh = (const float*)d_in[3];
    const float* bh = (const float*)d_in[4];
    float* out = (float*)d_out;

    const int smem_bytes = 65536 + 2 * 4 * SUBSZ * 2;   // 139,264 B
    cudaFuncSetAttribute(lstm_persist_kernel,
                         cudaFuncAttributeMaxDynamicSharedMemorySize, smem_bytes);

    gemm_f16_kernel<<<dim3(G4 / 128, (BB * TT) / 128), 256>>>(x, Wi, bi, bh);
    lstm_persist_kernel<<<GRID, 256, smem_bytes>>>(Wh, out);
}